// round 16
// baseline (speedup 1.0000x reference)
#include <cuda_runtime.h>
#include <cuda_fp16.h>
#include <cstdint>

#define NN 100000
#define EE 1600000
#define FULLMASK 0xffffffffu

__device__ float  g_proj[(size_t)2 * NN * 64];    // k, skip planes (fp32)
__device__ __half g_qv[(size_t)NN * 128];         // interleaved q/v fp16:
                                                  // [4p..4p+3] = {q2p,q2p+1,v2p,v2p+1}
__device__ float  g_scores[(size_t)EE * 4];       // deg>32 spill only
__device__ int    g_rowptr[NN + 1];

__device__ __forceinline__ unsigned h2u(__half2 h) {
    return *reinterpret_cast<unsigned*>(&h);
}
__device__ __forceinline__ float2 u2f2(unsigned u) {
    return __half22float2(*reinterpret_cast<__half2*>(&u));
}
__device__ __forceinline__ void ffma2(unsigned long long& d,
                                      unsigned long long a,
                                      unsigned long long b) {
    asm("fma.rn.f32x2 %0, %1, %2, %0;" : "+l"(d) : "l"(a), "l"(b));
}
__device__ __forceinline__ unsigned long long pack2(float lo, float hi) {
    unsigned long long r;
    asm("mov.b64 %0, {%1, %2};" : "=l"(r) : "f"(lo), "f"(hi));
    return r;
}
__device__ __forceinline__ void unpack2(unsigned long long p, float& lo, float& hi) {
    asm("mov.b64 {%0, %1}, %2;" : "=f"(lo), "=f"(hi) : "l"(p));
}

// ---------------------------------------------------------------------------
// K1: projection GEMM via HMMA + rowptr slice (blockIdx.y == 2).
// pp=0 -> {q(fp16, interleaved), k(fp32)}, pp=1 -> {v(fp16, interleaved), skip}.
// ---------------------------------------------------------------------------
__global__ void __launch_bounds__(256) proj_kernel(
    const float* __restrict__ feat,
    const int*   __restrict__ edst,
    const float* __restrict__ Wq, const float* __restrict__ bq,
    const float* __restrict__ Wk, const float* __restrict__ bk,
    const float* __restrict__ Wv, const float* __restrict__ bv,
    const float* __restrict__ Ws, const float* __restrict__ bs)
{
    __shared__ __half a_h[128][72];
    __shared__ __half b_h[128][72];

    const int tid = threadIdx.x;

    if (blockIdx.y == 2) {
        const int n = blockIdx.x * 256 + tid;
        if (n <= NN) {
            int lo = 0, hi = EE;
            while (lo < hi) {
                int mid = (lo + hi) >> 1;
                if (edst[mid] < n) lo = mid + 1; else hi = mid;
            }
            g_rowptr[n] = lo;
        }
        return;
    }

    const int rbase = blockIdx.x * 128;
    if (rbase >= NN) return;
    const int pp = blockIdx.y;
    const float* WA = pp ? Wv : Wq;
    const float* WB = pp ? Ws : Wk;
    const float* bA = pp ? bv : bq;
    const float* bB = pp ? bs : bk;

    for (int p = 0; p < 8; p++) {
        const int i = (p * 256 + tid) * 4;
        const int row = i >> 6, col = i & 63;
        const int grow = rbase + row;
        float4 f = make_float4(0.f, 0.f, 0.f, 0.f);
        if (grow < NN) f = *(const float4*)(feat + (size_t)grow * 64 + col);
        __half2 h0 = __floats2half2_rn(f.x, f.y);
        __half2 h1 = __floats2half2_rn(f.z, f.w);
        *(uint2*)&a_h[row][col] = make_uint2(h2u(h0), h2u(h1));
    }
    for (int p = 0; p < 32; p++) {
        const int i = p * 256 + tid;
        const int k = i >> 7, c = i & 127;
        const float w = ((c < 64) ? WA : WB)[k * 64 + (c & 63)];
        b_h[c][k] = __float2half_rn(w);
    }
    __syncthreads();

    const int wrp  = tid >> 5;
    const int lane = tid & 31;
    const int R = wrp * 16;
    const int r  = lane >> 2;
    const int cq = (lane & 3) * 2;

    unsigned af[4][4];
#pragma unroll
    for (int kk = 0; kk < 4; kk++) {
        const int k0 = kk * 16;
        af[kk][0] = *(const unsigned*)&a_h[R + r][k0 + cq];
        af[kk][1] = *(const unsigned*)&a_h[R + r + 8][k0 + cq];
        af[kk][2] = *(const unsigned*)&a_h[R + r][k0 + cq + 8];
        af[kk][3] = *(const unsigned*)&a_h[R + r + 8][k0 + cq + 8];
    }

    float acc[16][4];
#pragma unroll
    for (int t = 0; t < 16; t++) {
        const float* bb = (t < 8) ? bA : bB;
        const int cc = ((t * 8) & 63) + cq;
        acc[t][0] = bb[cc];     acc[t][1] = bb[cc + 1];
        acc[t][2] = bb[cc];     acc[t][3] = bb[cc + 1];
    }

#pragma unroll
    for (int kk = 0; kk < 4; kk++) {
        const int k0 = kk * 16;
#pragma unroll
        for (int t = 0; t < 16; t++) {
            const unsigned b0 = *(const unsigned*)&b_h[t * 8 + r][k0 + cq];
            const unsigned b1 = *(const unsigned*)&b_h[t * 8 + r][k0 + cq + 8];
            asm volatile(
                "mma.sync.aligned.m16n8k16.row.col.f32.f16.f16.f32 "
                "{%0,%1,%2,%3}, {%4,%5,%6,%7}, {%8,%9}, {%0,%1,%2,%3};\n"
                : "+f"(acc[t][0]), "+f"(acc[t][1]), "+f"(acc[t][2]), "+f"(acc[t][3])
                : "r"(af[kk][0]), "r"(af[kk][1]), "r"(af[kk][2]), "r"(af[kk][3]),
                  "r"(b0), "r"(b1));
        }
    }

    // epilogue: tiles 0-7 -> interleaved qv plane, 8-15 -> fp32 plane (k/skip)
    const int row0 = rbase + R + r;
    const int row1 = row0 + 8;
    // q pair (cc,cc+1) -> half offset 2*cc; v pair -> 2*cc + 2
    const int hoff = pp * 2;
    float* outf = g_proj + (size_t)pp * NN * 64;
#pragma unroll
    for (int t = 0; t < 8; t++) {
        const int cc = t * 8 + cq;
        if (row0 < NN)
            *(unsigned*)(g_qv + (size_t)row0 * 128 + 2 * cc + hoff) =
                h2u(__floats2half2_rn(acc[t][0], acc[t][1]));
        if (row1 < NN)
            *(unsigned*)(g_qv + (size_t)row1 * 128 + 2 * cc + hoff) =
                h2u(__floats2half2_rn(acc[t][2], acc[t][3]));
    }
#pragma unroll
    for (int t = 8; t < 16; t++) {
        const int cc = (t - 8) * 8 + cq;
        if (row0 < NN)
            *(float2*)(outf + (size_t)row0 * 64 + cc) = make_float2(acc[t][0], acc[t][1]);
        if (row1 < NN)
            *(float2*)(outf + (size_t)row1 * 64 + cc) = make_float2(acc[t][2], acc[t][3]);
    }
}

// ---------------------------------------------------------------------------
// K2: one warp per dst node, single-pass softmax aggregation.
// Interleaved qv plane: ONE LDG.128 per edge per lane ({q01,v01,q23,v23}).
// v-accumulate packed via fma.rn.f32x2 (issue-slot savings).
// ---------------------------------------------------------------------------
__global__ void __launch_bounds__(256) agg_fused_kernel(
    const int* __restrict__ esrc,
    const float* __restrict__ Wg, const float* __restrict__ bg,
    const float* __restrict__ ln_g, const float* __restrict__ ln_b,
    const float* __restrict__ prelu_a,
    float* __restrict__ out)
{
    __shared__ float  ks[8][64];
    __shared__ float4 wts[8][36];
    __shared__ int    srcs[8][36];

    const int wip  = threadIdx.x >> 5;
    const int lane = threadIdx.x & 31;
    const int node = blockIdx.x * 8 + wip;
    if (node >= NN) return;

    const int beg = g_rowptr[node];
    const int end = g_rowptr[node + 1];
    const int deg = end - beg;

    const float* kplane = g_proj;
    const float* splane = g_proj + (size_t)NN * 64;

    const float sk0 = splane[(size_t)node * 64 + lane];
    const float sk1 = splane[(size_t)node * 64 + lane + 32];

    ks[wip][lane]      = kplane[(size_t)node * 64 + lane];
    ks[wip][lane + 32] = kplane[(size_t)node * 64 + lane + 32];

    float acc0, acc1;

    if (deg <= 32) {
        if (lane < deg) srcs[wip][lane] = esrc[beg + lane];
        __syncwarp();

        const int grp = lane >> 4;
        const int l16 = lane & 15;
        const float4 kc = *(const float4*)(ks[wip] + l16 * 4);

        unsigned long long av01 = 0ull, av23 = 0ull;
        float den = 0.f;
        const int nIt = (deg + 3) >> 2;
        for (int it = 0; it < nIt; it++) {
            const int j0 = it * 4 + grp;
            const int j1 = j0 + 2;
            const bool vA = (j0 < deg), vB = (j1 < deg);
            const int jA = vA ? j0 : 0;
            const int jB = vB ? j1 : 0;
            const int srcA = srcs[wip][jA];
            const int srcB = srcs[wip][jB];
            // one LDG.128 per edge: {q01, v01, q23, v23}
            const uint4 eA = *(const uint4*)(g_qv + (size_t)srcA * 128 + l16 * 8);
            const uint4 eB = *(const uint4*)(g_qv + (size_t)srcB * 128 + l16 * 8);
            const float2 qA0 = u2f2(eA.x), qA1 = u2f2(eA.z);
            const float2 qB0 = u2f2(eB.x), qB1 = u2f2(eB.z);
            float pA = qA0.x*kc.x + qA0.y*kc.y + qA1.x*kc.z + qA1.y*kc.w;
            float pB = qB0.x*kc.x + qB0.y*kc.y + qB1.x*kc.z + qB1.y*kc.w;
            pA += __shfl_xor_sync(FULLMASK, pA, 1);
            pB += __shfl_xor_sync(FULLMASK, pB, 1);
            pA += __shfl_xor_sync(FULLMASK, pA, 2);
            pB += __shfl_xor_sync(FULLMASK, pB, 2);
            const float wA = vA ? __expf(pA * 0.25f) : 0.f;
            const float wB = vB ? __expf(pB * 0.25f) : 0.f;
            const float2 vA0 = u2f2(eA.y), vA1 = u2f2(eA.w);
            const float2 vB0 = u2f2(eB.y), vB1 = u2f2(eB.w);
            const unsigned long long wA2 = pack2(wA, wA);
            const unsigned long long wB2 = pack2(wB, wB);
            ffma2(av01, wA2, pack2(vA0.x, vA0.y));
            ffma2(av23, wA2, pack2(vA1.x, vA1.y));
            ffma2(av01, wB2, pack2(vB0.x, vB0.y));
            ffma2(av23, wB2, pack2(vB1.x, vB1.y));
            den += wA + wB;
        }
        float4 av;
        unpack2(av01, av.x, av.y);
        unpack2(av23, av.z, av.w);
        av.x += __shfl_xor_sync(FULLMASK, av.x, 16);
        av.y += __shfl_xor_sync(FULLMASK, av.y, 16);
        av.z += __shfl_xor_sync(FULLMASK, av.z, 16);
        av.w += __shfl_xor_sync(FULLMASK, av.w, 16);
        den  += __shfl_xor_sync(FULLMASK, den,  16);
        const float dinv = (den > 0.f) ? 1.f / den : 0.f;
        av.x *= dinv; av.y *= dinv; av.z *= dinv; av.w *= dinv;
        __syncwarp();
        if (lane < 16) *(float4*)(ks[wip] + l16 * 4) = av;
        __syncwarp();
        acc0 = ks[wip][lane];
        acc1 = ks[wip][lane + 32];
    } else {
        // ---- slow path (rare): chunked through g_scores, stabilized ----
        __syncwarp();
        const float* ksf = ks[wip];
        float mloc[4] = {-3e38f, -3e38f, -3e38f, -3e38f};
        for (int c = beg; c < end; c += 32) {
            const int e = c + lane;
            if (e < end) {
                const int src = esrc[e];
                const unsigned* qr = (const unsigned*)(g_qv + (size_t)src * 128);
                float a4[4] = {0.f, 0.f, 0.f, 0.f};
#pragma unroll
                for (int i = 0; i < 32; i++) {
                    const float2 f = u2f2(qr[2 * i]);     // q pair i
                    a4[i >> 3] += f.x * ksf[2 * i] + f.y * ksf[2 * i + 1];
                }
                float4 scv = make_float4(a4[0] * 0.25f, a4[1] * 0.25f,
                                         a4[2] * 0.25f, a4[3] * 0.25f);
                *(float4*)(g_scores + (size_t)e * 4) = scv;
                mloc[0] = fmaxf(mloc[0], scv.x); mloc[1] = fmaxf(mloc[1], scv.y);
                mloc[2] = fmaxf(mloc[2], scv.z); mloc[3] = fmaxf(mloc[3], scv.w);
            }
        }
#pragma unroll
        for (int off = 16; off; off >>= 1)
#pragma unroll
            for (int h = 0; h < 4; h++)
                mloc[h] = fmaxf(mloc[h], __shfl_xor_sync(FULLMASK, mloc[h], off));
        float sloc[4] = {0.f, 0.f, 0.f, 0.f};
        for (int c = beg; c < end; c += 32) {
            const int e = c + lane;
            if (e < end) {
                float4 scv = *(const float4*)(g_scores + (size_t)e * 4);
                float4 wv = make_float4(__expf(scv.x - mloc[0]), __expf(scv.y - mloc[1]),
                                        __expf(scv.z - mloc[2]), __expf(scv.w - mloc[3]));
                *(float4*)(g_scores + (size_t)e * 4) = wv;
                sloc[0] += wv.x; sloc[1] += wv.y; sloc[2] += wv.z; sloc[3] += wv.w;
            }
        }
#pragma unroll
        for (int off = 16; off; off >>= 1)
#pragma unroll
            for (int h = 0; h < 4; h++)
                sloc[h] += __shfl_xor_sync(FULLMASK, sloc[h], off);
        float inv[4];
#pragma unroll
        for (int h = 0; h < 4; h++)
            inv[h] = (sloc[h] > 0.f) ? 1.f / sloc[h] : 0.f;

        const bool lowh = (lane < 16);
        acc0 = 0.f; acc1 = 0.f;
        // v dim d -> half offset 4*(d>>1) + 2 + (d&1)
        const int d0 = lane,      o0 = 4 * (d0 >> 1) + 2 + (d0 & 1);
        const int d1 = lane + 32, o1 = 4 * (d1 >> 1) + 2 + (d1 & 1);
        for (int c = beg; c < end; c += 32) {
            const int e = c + lane;
            if (e < end) {
                float4 wv = *(const float4*)(g_scores + (size_t)e * 4);
                wts[wip][lane] = make_float4(wv.x * inv[0], wv.y * inv[1],
                                             wv.z * inv[2], wv.w * inv[3]);
            }
            __syncwarp();
            const int cnt = min(32, end - c);
            for (int j = 0; j < cnt; j++) {
                const float4 wt = wts[wip][j];
                const int src = esrc[c + j];
                const __half* vr = g_qv + (size_t)src * 128;
                const float wA = lowh ? wt.x : wt.y;
                const float wB = lowh ? wt.z : wt.w;
                acc0 += wA * __half2float(vr[o0]);
                acc1 += wB * __half2float(vr[o1]);
            }
            __syncwarp();
        }
    }

    // ---- gated skip ----
    float gp = sk0 * Wg[lane]      + acc0 * Wg[64 + lane] + (sk0 - acc0) * Wg[128 + lane]
             + sk1 * Wg[lane + 32] + acc1 * Wg[96 + lane] + (sk1 - acc1) * Wg[160 + lane];
#pragma unroll
    for (int off = 16; off; off >>= 1) gp += __shfl_xor_sync(FULLMASK, gp, off);
    const float gate = 1.f / (1.f + __expf(-(gp + bg[0])));
    const float r0 = gate * sk0 + (1.f - gate) * acc0;
    const float r1 = gate * sk1 + (1.f - gate) * acc1;

    // ---- LayerNorm + PReLU ----
    float sum = r0 + r1, sq = r0 * r0 + r1 * r1;
#pragma unroll
    for (int off = 16; off; off >>= 1) {
        sum += __shfl_xor_sync(FULLMASK, sum, off);
        sq  += __shfl_xor_sync(FULLMASK, sq,  off);
    }
    const float mu = sum * (1.f / 64.f);
    const float var = sq * (1.f / 64.f) - mu * mu;
    const float rstd = rsqrtf(var + 1e-5f);
    const float a = prelu_a[0];

    float o0 = (r0 - mu) * rstd * ln_g[lane]      + ln_b[lane];
    float o1 = (r1 - mu) * rstd * ln_g[lane + 32] + ln_b[lane + 32];
    o0 = (o0 >= 0.f) ? o0 : a * o0;
    o1 = (o1 >= 0.f) ? o1 : a * o1;
    out[(size_t)node * 64 + lane]      = o0;
    out[(size_t)node * 64 + lane + 32] = o1;
}

// ---------------------------------------------------------------------------
extern "C" void kernel_launch(void* const* d_in, const int* in_sizes, int n_in,
                              void* d_out, int out_size)
{
    const float* feat    = (const float*)d_in[0];
    const int*   esrc    = (const int*)  d_in[1];
    const int*   edst    = (const int*)  d_in[2];
    const float* Wq      = (const float*)d_in[3];
    const float* bq      = (const float*)d_in[4];
    const float* Wk      = (const float*)d_in[5];
    const float* bk      = (const float*)d_in[6];
    const float* Wv      = (const float*)d_in[7];
    const float* bv      = (const float*)d_in[8];
    const float* Ws      = (const float*)d_in[9];
    const float* bs      = (const float*)d_in[10];
    const float* Wg      = (const float*)d_in[11];
    const float* bg      = (const float*)d_in[12];
    const float* ln_g    = (const float*)d_in[13];
    const float* ln_b    = (const float*)d_in[14];
    const float* prelu_a = (const float*)d_in[15];
    float* out = (float*)d_out;

    proj_kernel<<<dim3((NN + 127) / 128, 3), 256>>>(feat, edst, Wq, bq, Wk, bk, Wv, bv, Ws, bs);
    agg_fused_kernel<<<(NN + 7) / 8, 256>>>(esrc, Wg, bg, ln_g, ln_b, prelu_a, out);
}